// round 6
// baseline (speedup 1.0000x reference)
#include <cuda_runtime.h>
#include <math.h>

// ---------------------------------------------------------------------------
// Problem constants
// ---------------------------------------------------------------------------
#define NB   1024   // batch
#define NC   32     // channels
#define LIN  1024   // input signal length
#define LRAW 1041   // conv output length (pad 16/16, k=16)
#define LP   520    // after avgpool(3,2)
#define L1   257    // after first 8/2 layer
#define L2   125    // after second 8/2 layer
#define L3   31     // after maxpool(4,4)
#define L4   12     // after final 8/2 layer
#define ZDIM 768    // 2*32*12

// ---------------------------------------------------------------------------
// Scratch (device globals; no runtime allocation allowed)
// ---------------------------------------------------------------------------
__device__ float  g_filt[NC * 16];
__device__ float  g_hp[NB * NC * LP];          // pooled conv output (pre-BN1 affine)
__device__ double g_st1[2 * NC];               // sum / sumsq for BN1 (over raw conv)
__device__ double g_st2[2 * NC];               // BN2 stats (over y1)
__device__ double g_st3[2 * NC];               // BN3 stats (over y2)
__device__ float  g_bn1[2 * NC];               // scale [0..NC), shift [NC..2NC)
__device__ float  g_bn2[2 * NC];
__device__ float  g_bn3[2 * NC];
__device__ float  g_y1[NB * NC * L3];
__device__ float  g_y2[NB * NC * L3];
__device__ float  g_z [NB * ZDIM];
__device__ float  g_c1[NB * 1024];
__device__ float  g_c2[NB * 512];
__device__ float  g_c3[NB * 128];

// ---------------------------------------------------------------------------
// K0: zero stats + build Laplace filter bank (double precision, 512 values)
// ---------------------------------------------------------------------------
__global__ void k_init(const float* __restrict__ la_a, const float* __restrict__ la_b) {
    int t = threadIdx.x;
    if (t < 2 * NC) { g_st1[t] = 0.0; g_st2[t] = 0.0; g_st3[t] = 0.0; }
    if (t < NC * 16) {
        int c = t >> 4, k = t & 15;
        const double A = 0.08, ep = 0.03, tal = 0.1, f = 50.0;
        const double w = 2.0 * 3.14159265358979323846 * f;
        const double q = 1.0 - ep * ep;
        double tk = (double)k / 15.0;
        double p  = tk - (double)la_b[c] / (double)la_a[c];
        double arg = w * (p - tal);
        double y = A * exp(-ep / sqrt(q) * arg) * (-sin(arg));
        g_filt[t] = (float)y;
    }
}

// ---------------------------------------------------------------------------
// K1: conv (pad 16/16) + la_bias + BN1 stats + avgpool(3,2)  -> g_hp
// One CTA per batch row; channels processed in groups of 8 through shared mem.
// ---------------------------------------------------------------------------
__global__ __launch_bounds__(256) void k_conv(const float* __restrict__ x,
                                              const float* __restrict__ la_bias) {
    __shared__ float sxp[LIN + 32];
    __shared__ float sf[NC * 16];
    __shared__ float sbias[NC];
    __shared__ float sraw[8 * LRAW];

    int b = blockIdx.x;
    int t = threadIdx.x;

    for (int i = t; i < LIN + 32; i += 256) {
        int xi = i - 16;
        sxp[i] = (xi >= 0 && xi < LIN) ? x[b * LIN + xi] : 0.0f;
    }
    for (int i = t; i < NC * 16; i += 256) sf[i] = g_filt[i];
    if (t < NC) sbias[t] = la_bias[t];
    __syncthreads();

    int wid = t >> 5, lane = t & 31;

    for (int g = 0; g < 4; g++) {
        int c0 = g * 8;
        // raw conv values for 8 channels
        for (int i = t; i < 8 * LRAW; i += 256) {
            int cl = i / LRAW, l = i - cl * LRAW;
            const float* fw = &sf[(c0 + cl) * 16];
            float acc = sbias[c0 + cl];
            #pragma unroll
            for (int k = 0; k < 16; k++) acc = fmaf(sxp[l + k], fw[k], acc);
            sraw[cl * LRAW + l] = acc;
        }
        __syncthreads();
        // BN1 stats: warp wid reduces channel c0+wid over all 1041 positions
        {
            double s = 0.0, ss = 0.0;
            const float* r = &sraw[wid * LRAW];
            for (int l = lane; l < LRAW; l += 32) {
                double v = (double)r[l];
                s += v; ss += v * v;
            }
            #pragma unroll
            for (int o = 16; o > 0; o >>= 1) {
                s  += __shfl_down_sync(0xffffffffu, s,  o);
                ss += __shfl_down_sync(0xffffffffu, ss, o);
            }
            if (lane == 0) {
                atomicAdd(&g_st1[c0 + wid],       s);
                atomicAdd(&g_st1[NC + c0 + wid],  ss);
            }
        }
        // avgpool(3,2)
        for (int i = t; i < 8 * LP; i += 256) {
            int cl = i / LP, l = i - cl * LP;
            const float* r = &sraw[cl * LRAW];
            float v = (r[2 * l] + r[2 * l + 1] + r[2 * l + 2]) * (1.0f / 3.0f);
            g_hp[(b * NC + c0 + cl) * LP + l] = v;
        }
        __syncthreads();
    }
}

// ---------------------------------------------------------------------------
// K2a / K2b: finalize BN affines (scale, shift)
// ---------------------------------------------------------------------------
__global__ void k_bnfin1(const float* __restrict__ gg, const float* __restrict__ bb) {
    int c = threadIdx.x;
    if (c < NC) {
        double N = (double)NB * (double)LRAW;
        double m = g_st1[c] / N;
        double v = g_st1[NC + c] / N - m * m;
        float sc = gg[c] * rsqrtf((float)v + 1e-5f);
        g_bn1[c] = sc;
        g_bn1[NC + c] = bb[c] - (float)m * sc;
    }
}

__global__ void k_bnfin23(const float* __restrict__ g2, const float* __restrict__ b2v,
                          const float* __restrict__ g3, const float* __restrict__ b3v) {
    int c = threadIdx.x;
    if (c < NC) {
        double N = (double)NB * (double)L3;
        double m2 = g_st2[c] / N, v2 = g_st2[NC + c] / N - m2 * m2;
        float sc2 = g2[c] * rsqrtf((float)v2 + 1e-5f);
        g_bn2[c] = sc2; g_bn2[NC + c] = b2v[c] - (float)m2 * sc2;
        double m3 = g_st3[c] / N, v3 = g_st3[NC + c] / N - m3 * m3;
        float sc3 = g3[c] * rsqrtf((float)v3 + 1e-5f);
        g_bn3[c] = sc3; g_bn3[NC + c] = b3v[c] - (float)m3 * sc3;
    }
}

// ---------------------------------------------------------------------------
// K3: both branches up to maxpool: BN1-affine -> (Always->Eventually) and
// (Eventually->Always) -> maxpool(4,4) -> y1/y2 + BN2/BN3 stats
// One CTA per batch row, channel groups of 8 in shared memory.
// ---------------------------------------------------------------------------
__global__ __launch_bounds__(256) void k_branch(
    const float* __restrict__ a1_w, const float* __restrict__ a1_b,
    const float* __restrict__ e1_w, const float* __restrict__ e1_b,
    const float* __restrict__ f1_w, const float* __restrict__ f1_b,
    const float* __restrict__ fa_w, const float* __restrict__ fa_b) {

    __shared__ float shbn[8 * LP];
    __shared__ float s1[8 * L1];
    __shared__ float s2[8 * L2];
    __shared__ float sw_a1[NC * 8], sw_e1[NC * 8], sw_f1[NC * 8], sw_fa[NC * 8];
    __shared__ float sb_a1[NC], sb_e1[NC], sb_f1[NC], sb_fa[NC];
    __shared__ float ssum_a1[NC], ssum_fa[NC];
    __shared__ float sbn1[2 * NC];

    int b = blockIdx.x;
    int t = threadIdx.x;
    int wid = t >> 5, lane = t & 31;

    if (t < NC * 8) { sw_a1[t] = a1_w[t]; sw_e1[t] = e1_w[t]; sw_f1[t] = f1_w[t]; sw_fa[t] = fa_w[t]; }
    if (t < NC) {
        sb_a1[t] = a1_b[t]; sb_e1[t] = e1_b[t]; sb_f1[t] = f1_b[t]; sb_fa[t] = fa_b[t];
        float sa = 0.0f, sfw = 0.0f;
        for (int j = 0; j < 8; j++) { sa += a1_w[t * 8 + j]; sfw += fa_w[t * 8 + j]; }
        ssum_a1[t] = sa; ssum_fa[t] = sfw;
    }
    if (t < 2 * NC) sbn1[t] = g_bn1[t];
    __syncthreads();

    for (int g = 0; g < 4; g++) {
        int c0 = g * 8;
        // BN1-affine input
        for (int i = t; i < 8 * LP; i += 256) {
            int cl = i / LP, l = i - cl * LP;
            int c = c0 + cl;
            shbn[i] = g_hp[(b * NC + c) * LP + l] * sbn1[c] + sbn1[NC + c];
        }
        __syncthreads();

        // ----- branch 1: Always(a1) -----
        for (int i = t; i < 8 * L1; i += 256) {
            int cl = i / L1, n = i - cl * L1;
            int c = c0 + cl;
            float acc = sb_a1[c] - ssum_a1[c];
            const float* w = &sw_a1[c * 8];
            const float* p = &shbn[cl * LP + 2 * n];
            #pragma unroll
            for (int j = 0; j < 8; j++) acc = fmaf(p[j], w[j], acc);
            s1[i] = fmaxf(acc, 0.0f);
        }
        __syncthreads();
        // Eventually(e1)
        for (int i = t; i < 8 * L2; i += 256) {
            int cl = i / L2, n = i - cl * L2;
            int c = c0 + cl;
            float acc = 1.0f - sb_e1[c];
            const float* w = &sw_e1[c * 8];
            const float* p = &s1[cl * L1 + 2 * n];
            #pragma unroll
            for (int j = 0; j < 8; j++) acc = fmaf(p[j], w[j], acc);
            s2[i] = fmaxf(acc, 0.0f);
        }
        __syncthreads();
        // maxpool(4,4) + BN2 stats (warp wid -> channel c0+wid)
        {
            int c = c0 + wid;
            double s = 0.0, ss = 0.0;
            if (lane < L3) {
                const float* p = &s2[wid * L2 + 4 * lane];
                float y = fmaxf(fmaxf(p[0], p[1]), fmaxf(p[2], p[3]));
                g_y1[(b * NC + c) * L3 + lane] = y;
                s = (double)y; ss = (double)y * (double)y;
            }
            #pragma unroll
            for (int o = 16; o > 0; o >>= 1) {
                s  += __shfl_down_sync(0xffffffffu, s,  o);
                ss += __shfl_down_sync(0xffffffffu, ss, o);
            }
            if (lane == 0) { atomicAdd(&g_st2[c], s); atomicAdd(&g_st2[NC + c], ss); }
        }
        __syncthreads();

        // ----- branch 2: Eventually(f1) -----
        for (int i = t; i < 8 * L1; i += 256) {
            int cl = i / L1, n = i - cl * L1;
            int c = c0 + cl;
            float acc = 1.0f - sb_f1[c];
            const float* w = &sw_f1[c * 8];
            const float* p = &shbn[cl * LP + 2 * n];
            #pragma unroll
            for (int j = 0; j < 8; j++) acc = fmaf(p[j], w[j], acc);
            s1[i] = fmaxf(acc, 0.0f);
        }
        __syncthreads();
        // Always(fa)
        for (int i = t; i < 8 * L2; i += 256) {
            int cl = i / L2, n = i - cl * L2;
            int c = c0 + cl;
            float acc = sb_fa[c] - ssum_fa[c];
            const float* w = &sw_fa[c * 8];
            const float* p = &s1[cl * L1 + 2 * n];
            #pragma unroll
            for (int j = 0; j < 8; j++) acc = fmaf(p[j], w[j], acc);
            s2[i] = fmaxf(acc, 0.0f);
        }
        __syncthreads();
        // maxpool(4,4) + BN3 stats
        {
            int c = c0 + wid;
            double s = 0.0, ss = 0.0;
            if (lane < L3) {
                const float* p = &s2[wid * L2 + 4 * lane];
                float y = fmaxf(fmaxf(p[0], p[1]), fmaxf(p[2], p[3]));
                g_y2[(b * NC + c) * L3 + lane] = y;
                s = (double)y; ss = (double)y * (double)y;
            }
            #pragma unroll
            for (int o = 16; o > 0; o >>= 1) {
                s  += __shfl_down_sync(0xffffffffu, s,  o);
                ss += __shfl_down_sync(0xffffffffu, ss, o);
            }
            if (lane == 0) { atomicAdd(&g_st3[c], s); atomicAdd(&g_st3[NC + c], ss); }
        }
        __syncthreads();
    }
}

// ---------------------------------------------------------------------------
// K5: BN2/BN3 affine + final Eventually (31->12) for both branches -> z (B,768)
// ---------------------------------------------------------------------------
__global__ __launch_bounds__(256) void k_zassm(
    const float* __restrict__ e2_w, const float* __restrict__ e2_b,
    const float* __restrict__ f2_w, const float* __restrict__ f2_b) {
    int b = blockIdx.x;
    for (int o = threadIdx.x; o < ZDIM; o += 256) {
        int br  = o / 384;
        int rem = o - br * 384;
        int c = rem / L4, n = rem - c * L4;
        const float* y  = br ? &g_y2[(b * NC + c) * L3] : &g_y1[(b * NC + c) * L3];
        const float* bn = br ? g_bn3 : g_bn2;
        const float* w  = br ? &f2_w[c * 8] : &e2_w[c * 8];
        float bb = br ? f2_b[c] : e2_b[c];
        float sc = bn[c], sh = bn[NC + c];
        float acc = 1.0f - bb;
        #pragma unroll
        for (int j = 0; j < 8; j++)
            acc = fmaf(y[2 * n + j] * sc + sh, w[j], acc);
        g_z[b * ZDIM + o] = fmaxf(acc, 0.0f);
    }
}

// ---------------------------------------------------------------------------
// Tiled fp32 GEMM with fused bias + relu: C = relu(A[MxK] @ W[KxN] + bias)
// BM=BN=64, BK=16, 256 threads, 4x4 micro-tile. M%64==0, N%64==0, K%16==0.
// ---------------------------------------------------------------------------
__global__ __launch_bounds__(256) void k_gemm_relu(
    const float* __restrict__ A, const float* __restrict__ W,
    const float* __restrict__ bias, float* __restrict__ Cc,
    int M, int N, int K) {
    __shared__ float As[16][68];   // [k][m], padded
    __shared__ float Ws[16][64];   // [k][n]

    int tid = threadIdx.x;
    int tx = tid & 15, ty = tid >> 4;
    int rowBase = blockIdx.y * 64;
    int colBase = blockIdx.x * 64;

    int aRow = tid >> 2, aCol = (tid & 3) * 4;
    int wRow = tid >> 4, wCol = (tid & 15) * 4;

    float acc[4][4] = {};

    for (int kt = 0; kt < K; kt += 16) {
        float4 av = *reinterpret_cast<const float4*>(&A[(rowBase + aRow) * K + kt + aCol]);
        As[aCol + 0][aRow] = av.x;
        As[aCol + 1][aRow] = av.y;
        As[aCol + 2][aRow] = av.z;
        As[aCol + 3][aRow] = av.w;
        float4 wv = *reinterpret_cast<const float4*>(&W[(kt + wRow) * N + colBase + wCol]);
        *reinterpret_cast<float4*>(&Ws[wRow][wCol]) = wv;
        __syncthreads();
        #pragma unroll
        for (int k = 0; k < 16; k++) {
            float4 a = *reinterpret_cast<const float4*>(&As[k][ty * 4]);
            float4 w = *reinterpret_cast<const float4*>(&Ws[k][tx * 4]);
            float aa[4] = { a.x, a.y, a.z, a.w };
            float ww[4] = { w.x, w.y, w.z, w.w };
            #pragma unroll
            for (int i = 0; i < 4; i++)
                #pragma unroll
                for (int j = 0; j < 4; j++)
                    acc[i][j] = fmaf(aa[i], ww[j], acc[i][j]);
        }
        __syncthreads();
    }

    #pragma unroll
    for (int i = 0; i < 4; i++) {
        int r = rowBase + ty * 4 + i;
        #pragma unroll
        for (int j = 0; j < 4; j++) {
            int cidx = colBase + tx * 4 + j;
            Cc[r * N + cidx] = fmaxf(acc[i][j] + bias[cidx], 0.0f);
        }
    }
}

// ---------------------------------------------------------------------------
// Final FC: (B,128) @ (128,10) + bias, relu. One warp per batch row.
// ---------------------------------------------------------------------------
__global__ __launch_bounds__(256) void k_fc4(const float* __restrict__ w4,
                                             const float* __restrict__ b4,
                                             float* __restrict__ out) {
    int b = blockIdx.x * 8 + (threadIdx.x >> 5);
    int lane = threadIdx.x & 31;
    const float* row = &g_c3[b * 128];
    float v0 = row[lane], v1 = row[lane + 32], v2 = row[lane + 64], v3 = row[lane + 96];
    for (int j = 0; j < 10; j++) {
        float p = v0 * w4[lane * 10 + j]
                + v1 * w4[(lane + 32) * 10 + j]
                + v2 * w4[(lane + 64) * 10 + j]
                + v3 * w4[(lane + 96) * 10 + j];
        #pragma unroll
        for (int o = 16; o > 0; o >>= 1) p += __shfl_down_sync(0xffffffffu, p, o);
        if (lane == 0) out[b * 10 + j] = fmaxf(p + b4[j], 0.0f);
    }
}

// ---------------------------------------------------------------------------
// Launch
// ---------------------------------------------------------------------------
extern "C" void kernel_launch(void* const* d_in, const int* in_sizes, int n_in,
                              void* d_out, int out_size) {
    const float* x       = (const float*)d_in[0];
    const float* la_a    = (const float*)d_in[1];
    const float* la_b    = (const float*)d_in[2];
    const float* la_bias = (const float*)d_in[3];
    const float* bn1_g   = (const float*)d_in[4];
    const float* bn1_b   = (const float*)d_in[5];
    const float* a1_w    = (const float*)d_in[6];
    const float* a1_b    = (const float*)d_in[7];
    const float* e1_w    = (const float*)d_in[8];
    const float* e1_b    = (const float*)d_in[9];
    const float* bn2_g   = (const float*)d_in[10];
    const float* bn2_b   = (const float*)d_in[11];
    const float* e2_w    = (const float*)d_in[12];
    const float* e2_b    = (const float*)d_in[13];
    const float* f1_w    = (const float*)d_in[14];
    const float* f1_b    = (const float*)d_in[15];
    const float* fa_w    = (const float*)d_in[16];
    const float* fa_b    = (const float*)d_in[17];
    const float* bn3_g   = (const float*)d_in[18];
    const float* bn3_b   = (const float*)d_in[19];
    const float* f2_w    = (const float*)d_in[20];
    const float* f2_b    = (const float*)d_in[21];
    const float* w1      = (const float*)d_in[22];
    const float* b1      = (const float*)d_in[23];
    const float* w2      = (const float*)d_in[24];
    const float* b2      = (const float*)d_in[25];
    const float* w3      = (const float*)d_in[26];
    const float* b3      = (const float*)d_in[27];
    const float* w4      = (const float*)d_in[28];
    const float* b4      = (const float*)d_in[29];
    float* out = (float*)d_out;

    // Resolve scratch symbol addresses (host API, not a stream op; capture-safe).
    float *p_z = nullptr, *p_c1 = nullptr, *p_c2 = nullptr, *p_c3 = nullptr;
    cudaGetSymbolAddress((void**)&p_z,  g_z);
    cudaGetSymbolAddress((void**)&p_c1, g_c1);
    cudaGetSymbolAddress((void**)&p_c2, g_c2);
    cudaGetSymbolAddress((void**)&p_c3, g_c3);

    k_init<<<1, 512>>>(la_a, la_b);
    k_conv<<<NB, 256>>>(x, la_bias);
    k_bnfin1<<<1, 32>>>(bn1_g, bn1_b);
    k_branch<<<NB, 256>>>(a1_w, a1_b, e1_w, e1_b, f1_w, f1_b, fa_w, fa_b);
    k_bnfin23<<<1, 32>>>(bn2_g, bn2_b, bn3_g, bn3_b);
    k_zassm<<<NB, 256>>>(e2_w, e2_b, f2_w, f2_b);

    // FC chain
    {
        dim3 g(1024 / 64, NB / 64);
        k_gemm_relu<<<g, 256>>>(p_z, w1, b1, p_c1, NB, 1024, 768);
    }
    {
        dim3 g(512 / 64, NB / 64);
        k_gemm_relu<<<g, 256>>>(p_c1, w2, b2, p_c2, NB, 512, 1024);
    }
    {
        dim3 g(128 / 64, NB / 64);
        k_gemm_relu<<<g, 256>>>(p_c2, w3, b3, p_c3, NB, 128, 512);
    }
    k_fc4<<<NB / 8, 256>>>(w4, b4, out);
}

// round 7
// speedup vs baseline: 3.0276x; 3.0276x over previous
#include <cuda_runtime.h>
#include <math.h>

// ---------------------------------------------------------------------------
// Problem constants
// ---------------------------------------------------------------------------
#define NB   1024   // batch
#define NC   32     // channels
#define LIN  1024   // input signal length
#define LRAW 1041   // conv output length (pad 16/16, k=16)
#define LP   520    // after avgpool(3,2)
#define L1   257    // after first 8/2 layer (index 256 never consumed)
#define L2   125    // after second 8/2 layer
#define L3   31     // after maxpool(4,4)
#define L4   12     // after final 8/2 layer
#define ZDIM 768    // 2*32*12

// ---------------------------------------------------------------------------
// Scratch (device globals; no runtime allocation allowed)
// ---------------------------------------------------------------------------
__device__ float  g_filt[NC * 16];
__device__ float  g_hp[NB * NC * LP];          // pooled conv output (pre-BN1 affine)
__device__ float  g_st1[2 * NC];               // sum / sumsq for BN1 (over raw conv)
__device__ float  g_st2[2 * NC];               // BN2 stats (over y1)
__device__ float  g_st3[2 * NC];               // BN3 stats (over y2)
__device__ float  g_bn1[2 * NC];               // scale [0..NC), shift [NC..2NC)
__device__ float  g_bn2[2 * NC];
__device__ float  g_bn3[2 * NC];
__device__ float  g_y1[NB * NC * L3];
__device__ float  g_y2[NB * NC * L3];
__device__ float  g_z [NB * ZDIM];
__device__ float  g_c1[NB * 1024];
__device__ float  g_c2[NB * 512];
__device__ float  g_c3[NB * 128];

// ---------------------------------------------------------------------------
// K0: zero stats + build Laplace filter bank (double precision, 512 values)
// ---------------------------------------------------------------------------
__global__ void k_init(const float* __restrict__ la_a, const float* __restrict__ la_b) {
    int t = threadIdx.x;
    if (t < 2 * NC) { g_st1[t] = 0.0f; g_st2[t] = 0.0f; g_st3[t] = 0.0f; }
    if (t < NC * 16) {
        int c = t >> 4, k = t & 15;
        const double A = 0.08, ep = 0.03, tal = 0.1, f = 50.0;
        const double w = 2.0 * 3.14159265358979323846 * f;
        const double q = 1.0 - ep * ep;
        double tk = (double)k / 15.0;
        double p  = tk - (double)la_b[c] / (double)la_a[c];
        double arg = w * (p - tal);
        double y = A * exp(-ep / sqrt(q) * arg) * (-sin(arg));
        g_filt[t] = (float)y;
    }
}

// ---------------------------------------------------------------------------
// K1: conv (pad 16/16) + la_bias + BN1 stats + avgpool(3,2)  -> g_hp
// One CTA per batch row; warp-per-channel, 5 overlapping outputs per lane
// iteration from 5 LDS.128 (20 floats -> 80 FMA). Stats+pool fused in regs.
// ---------------------------------------------------------------------------
__global__ __launch_bounds__(256) void k_conv(const float* __restrict__ x,
                                              const float* __restrict__ la_bias) {
    __shared__ float sxp[1060];   // 16 left pad + 1024 + right pad/zero to 1060

    int b = blockIdx.x;
    int t = threadIdx.x;

    for (int i = t; i < 1060; i += 256) {
        int xi = i - 16;
        sxp[i] = (xi >= 0 && xi < LIN) ? x[b * LIN + xi] : 0.0f;
    }
    __syncthreads();

    int w = t >> 5, lane = t & 31;

    #pragma unroll 1
    for (int cc = 0; cc < 4; cc++) {
        int c = w * 4 + cc;
        float f[16];
        #pragma unroll
        for (int k = 0; k < 16; k++) f[k] = g_filt[c * 16 + k];
        float bias = la_bias[c];

        float s = 0.0f, ss = 0.0f;
        float* hprow = &g_hp[(b * NC + c) * LP];

        #pragma unroll 1
        for (int i = 0; i < 9; i++) {
            int base = 4 * lane + 128 * i;       // multiple of 4 -> 16B aligned
            if (base > 1040) continue;
            float win[20];
            #pragma unroll
            for (int j = 0; j < 5; j++) {
                float4 q = *reinterpret_cast<const float4*>(&sxp[base + 4 * j]);
                win[4 * j + 0] = q.x; win[4 * j + 1] = q.y;
                win[4 * j + 2] = q.z; win[4 * j + 3] = q.w;
            }
            float r0 = bias, r1 = bias, r2 = bias, r3 = bias, r4 = bias;
            #pragma unroll
            for (int k = 0; k < 16; k++) {
                float fk = f[k];
                r0 = fmaf(win[k    ], fk, r0);
                r1 = fmaf(win[k + 1], fk, r1);
                r2 = fmaf(win[k + 2], fk, r2);
                r3 = fmaf(win[k + 3], fk, r3);
                r4 = fmaf(win[k + 4], fk, r4);
            }
            // BN1 stats over raw conv (positions base..base+3, <=1040)
            if (base + 0 <= 1040) { s += r0; ss = fmaf(r0, r0, ss); }
            if (base + 1 <= 1040) { s += r1; ss = fmaf(r1, r1, ss); }
            if (base + 2 <= 1040) { s += r2; ss = fmaf(r2, r2, ss); }
            if (base + 3 <= 1040) { s += r3; ss = fmaf(r3, r3, ss); }
            // avgpool(3,2): pooled[m0] and pooled[m0+1]
            int m0 = base >> 1;
            if (m0 <= 518) {
                float2 pv;
                pv.x = (r0 + r1 + r2) * (1.0f / 3.0f);
                pv.y = (r2 + r3 + r4) * (1.0f / 3.0f);
                *reinterpret_cast<float2*>(&hprow[m0]) = pv;
            }
        }
        #pragma unroll
        for (int o = 16; o > 0; o >>= 1) {
            s  += __shfl_down_sync(0xffffffffu, s,  o);
            ss += __shfl_down_sync(0xffffffffu, ss, o);
        }
        if (lane == 0) {
            atomicAdd(&g_st1[c],      s);
            atomicAdd(&g_st1[NC + c], ss);
        }
    }
}

// ---------------------------------------------------------------------------
// K2a / K2b: finalize BN affines (scale, shift)
// ---------------------------------------------------------------------------
__global__ void k_bnfin1(const float* __restrict__ gg, const float* __restrict__ bb) {
    int c = threadIdx.x;
    if (c < NC) {
        float N = (float)NB * (float)LRAW;
        float m = g_st1[c] / N;
        float v = g_st1[NC + c] / N - m * m;
        float sc = gg[c] * rsqrtf(v + 1e-5f);
        g_bn1[c] = sc;
        g_bn1[NC + c] = bb[c] - m * sc;
    }
}

__global__ void k_bnfin23(const float* __restrict__ g2, const float* __restrict__ b2v,
                          const float* __restrict__ g3, const float* __restrict__ b3v) {
    int c = threadIdx.x;
    if (c < NC) {
        float N = (float)NB * (float)L3;
        float m2 = g_st2[c] / N, v2 = g_st2[NC + c] / N - m2 * m2;
        float sc2 = g2[c] * rsqrtf(v2 + 1e-5f);
        g_bn2[c] = sc2; g_bn2[NC + c] = b2v[c] - m2 * sc2;
        float m3 = g_st3[c] / N, v3 = g_st3[NC + c] / N - m3 * m3;
        float sc3 = g3[c] * rsqrtf(v3 + 1e-5f);
        g_bn3[c] = sc3; g_bn3[NC + c] = b3v[c] - m3 * sc3;
    }
}

// ---------------------------------------------------------------------------
// K3: both branches up to maxpool. Warp-per-channel, warp-private shared rows,
// no __syncthreads in hot loop. Layer2 + maxpool entirely in registers.
// ---------------------------------------------------------------------------
__global__ __launch_bounds__(256) void k_branch(
    const float* __restrict__ a1_w, const float* __restrict__ a1_b,
    const float* __restrict__ e1_w, const float* __restrict__ e1_b,
    const float* __restrict__ f1_w, const float* __restrict__ f1_b,
    const float* __restrict__ fa_w, const float* __restrict__ fa_b) {

    // per-warp: in[528] (520 used) + s1[264] (256 used, pad for over-read)
    __shared__ float sh[8][792];

    int b = blockIdx.x;
    int t = threadIdx.x;
    int w = t >> 5, lane = t & 31;

    float* in = sh[w];
    float* s1 = sh[w] + 528;

    #pragma unroll 1
    for (int cc = 0; cc < 4; cc++) {
        int c = w * 4 + cc;
        float sc = g_bn1[c], sf = g_bn1[NC + c];
        const float* hprow = &g_hp[(b * NC + c) * LP];

        __syncwarp();
        // stage A: BN1-affine input into warp-private shared (float4)
        #pragma unroll
        for (int i = 0; i < 5; i++) {
            int idx = lane + 32 * i;            // 130 float4s
            if (idx < 130) {
                float4 v = reinterpret_cast<const float4*>(hprow)[idx];
                v.x = fmaf(v.x, sc, sf); v.y = fmaf(v.y, sc, sf);
                v.z = fmaf(v.z, sc, sf); v.w = fmaf(v.w, sc, sf);
                *reinterpret_cast<float4*>(&in[4 * idx]) = v;
            }
        }
        __syncwarp();

        // ===== two branches: (Always,Eventually)->g_y1/st2 ; (Eventually,Always)->g_y2/st3
        #pragma unroll 1
        for (int br = 0; br < 2; br++) {
            // layer-1 weights/bias
            float w1r[8], acc1;
            if (br == 0) {
                float sum = 0.0f;
                #pragma unroll
                for (int j = 0; j < 8; j++) { w1r[j] = a1_w[c * 8 + j]; sum += w1r[j]; }
                acc1 = a1_b[c] - sum;                      // Always
            } else {
                #pragma unroll
                for (int j = 0; j < 8; j++) w1r[j] = f1_w[c * 8 + j];
                acc1 = 1.0f - f1_b[c];                     // Eventually
            }

            // layer 1: 256 outputs (2 iters x 32 lanes x 4), s1[256] never used
            #pragma unroll
            for (int i = 0; i < 2; i++) {
                int n0 = 4 * lane + 128 * i;
                int base = 2 * n0;                          // 16B aligned
                float win[16];
                #pragma unroll
                for (int j = 0; j < 4; j++) {
                    float4 q = *reinterpret_cast<const float4*>(&in[base + 4 * j]);
                    win[4 * j + 0] = q.x; win[4 * j + 1] = q.y;
                    win[4 * j + 2] = q.z; win[4 * j + 3] = q.w;
                }
                float r0 = acc1, r1 = acc1, r2 = acc1, r3 = acc1;
                #pragma unroll
                for (int k = 0; k < 8; k++) {
                    float wk = w1r[k];
                    r0 = fmaf(win[k    ], wk, r0);
                    r1 = fmaf(win[k + 2], wk, r1);
                    r2 = fmaf(win[k + 4], wk, r2);
                    r3 = fmaf(win[k + 6], wk, r3);
                }
                float4 o;
                o.x = fmaxf(r0, 0.0f); o.y = fmaxf(r1, 0.0f);
                o.z = fmaxf(r2, 0.0f); o.w = fmaxf(r3, 0.0f);
                *reinterpret_cast<float4*>(&s1[n0]) = o;
            }
            __syncwarp();

            // layer-2 weights/bias
            float w2r[8], acc2;
            if (br == 0) {
                #pragma unroll
                for (int j = 0; j < 8; j++) w2r[j] = e1_w[c * 8 + j];
                acc2 = 1.0f - e1_b[c];                     // Eventually
            } else {
                float sum = 0.0f;
                #pragma unroll
                for (int j = 0; j < 8; j++) { w2r[j] = fa_w[c * 8 + j]; sum += w2r[j]; }
                acc2 = fa_b[c] - sum;                      // Always
            }

            // layer 2 (125 outs) + maxpool(4,4): lane l owns s2[4l..4l+3] -> pool l
            {
                int base = 8 * lane;                       // reads s1[base..base+13] (pad ok)
                float win[16];
                #pragma unroll
                for (int j = 0; j < 4; j++) {
                    float4 q = *reinterpret_cast<const float4*>(&s1[base + 4 * j]);
                    win[4 * j + 0] = q.x; win[4 * j + 1] = q.y;
                    win[4 * j + 2] = q.z; win[4 * j + 3] = q.w;
                }
                float r0 = acc2, r1 = acc2, r2 = acc2, r3 = acc2;
                #pragma unroll
                for (int k = 0; k < 8; k++) {
                    float wk = w2r[k];
                    r0 = fmaf(win[k    ], wk, r0);
                    r1 = fmaf(win[k + 2], wk, r1);
                    r2 = fmaf(win[k + 4], wk, r2);
                    r3 = fmaf(win[k + 6], wk, r3);
                }
                r0 = fmaxf(r0, 0.0f); r1 = fmaxf(r1, 0.0f);
                r2 = fmaxf(r2, 0.0f); r3 = fmaxf(r3, 0.0f);
                float y = fmaxf(fmaxf(r0, r1), fmaxf(r2, r3));
                float s = 0.0f, ss = 0.0f;
                if (lane < L3) {
                    if (br == 0) g_y1[(b * NC + c) * L3 + lane] = y;
                    else         g_y2[(b * NC + c) * L3 + lane] = y;
                    s = y; ss = y * y;
                }
                #pragma unroll
                for (int o = 16; o > 0; o >>= 1) {
                    s  += __shfl_down_sync(0xffffffffu, s,  o);
                    ss += __shfl_down_sync(0xffffffffu, ss, o);
                }
                if (lane == 0) {
                    float* st = (br == 0) ? g_st2 : g_st3;
                    atomicAdd(&st[c],      s);
                    atomicAdd(&st[NC + c], ss);
                }
            }
            __syncwarp();
        }
    }
}

// ---------------------------------------------------------------------------
// K5: BN2/BN3 affine + final Eventually (31->12) for both branches -> z (B,768)
// ---------------------------------------------------------------------------
__global__ __launch_bounds__(256) void k_zassm(
    const float* __restrict__ e2_w, const float* __restrict__ e2_b,
    const float* __restrict__ f2_w, const float* __restrict__ f2_b) {
    int b = blockIdx.x;
    for (int o = threadIdx.x; o < ZDIM; o += 256) {
        int br  = o / 384;
        int rem = o - br * 384;
        int c = rem / L4, n = rem - c * L4;
        const float* y  = br ? &g_y2[(b * NC + c) * L3] : &g_y1[(b * NC + c) * L3];
        const float* bn = br ? g_bn3 : g_bn2;
        const float* wv = br ? &f2_w[c * 8] : &e2_w[c * 8];
        float bb = br ? f2_b[c] : e2_b[c];
        float scv = bn[c], shv = bn[NC + c];
        float acc = 1.0f - bb;
        #pragma unroll
        for (int j = 0; j < 8; j++)
            acc = fmaf(fmaf(y[2 * n + j], scv, shv), wv[j], acc);
        g_z[b * ZDIM + o] = fmaxf(acc, 0.0f);
    }
}

// ---------------------------------------------------------------------------
// Tiled fp32 GEMM with fused bias + relu: C = relu(A[MxK] @ W[KxN] + bias)
// BM=BN=64, BK=16, 256 threads, 4x4 micro-tile, register prefetch of next
// K-tile overlapped with compute. M%64==0, N%64==0, K%16==0.
// ---------------------------------------------------------------------------
__global__ __launch_bounds__(256) void k_gemm_relu(
    const float* __restrict__ A, const float* __restrict__ W,
    const float* __restrict__ bias, float* __restrict__ Cc,
    int M, int N, int K) {
    __shared__ float As[16][68];   // [k][m], padded
    __shared__ float Ws[16][64];   // [k][n]

    int tid = threadIdx.x;
    int tx = tid & 15, ty = tid >> 4;
    int rowBase = blockIdx.y * 64;
    int colBase = blockIdx.x * 64;

    int aRow = tid >> 2, aCol = (tid & 3) * 4;
    int wRow = tid >> 4, wCol = (tid & 15) * 4;

    const float* Aptr = A + (rowBase + aRow) * K + aCol;
    const float* Wptr = W + wRow * N + colBase + wCol;

    float4 av = *reinterpret_cast<const float4*>(Aptr);
    float4 wv = *reinterpret_cast<const float4*>(Wptr);

    float acc[4][4] = {};

    for (int kt = 0; kt < K; kt += 16) {
        __syncthreads();
        As[aCol + 0][aRow] = av.x;
        As[aCol + 1][aRow] = av.y;
        As[aCol + 2][aRow] = av.z;
        As[aCol + 3][aRow] = av.w;
        *reinterpret_cast<float4*>(&Ws[wRow][wCol]) = wv;
        __syncthreads();
        if (kt + 16 < K) {
            av = *reinterpret_cast<const float4*>(Aptr + kt + 16);
            wv = *reinterpret_cast<const float4*>(Wptr + (kt + 16) * N);
        }
        #pragma unroll
        for (int k = 0; k < 16; k++) {
            float4 a = *reinterpret_cast<const float4*>(&As[k][ty * 4]);
            float4 ww = *reinterpret_cast<const float4*>(&Ws[k][tx * 4]);
            float aa[4] = { a.x, a.y, a.z, a.w };
            float wb[4] = { ww.x, ww.y, ww.z, ww.w };
            #pragma unroll
            for (int i = 0; i < 4; i++)
                #pragma unroll
                for (int j = 0; j < 4; j++)
                    acc[i][j] = fmaf(aa[i], wb[j], acc[i][j]);
        }
    }

    float4 bv = *reinterpret_cast<const float4*>(&bias[colBase + tx * 4]);
    float bj[4] = { bv.x, bv.y, bv.z, bv.w };
    #pragma unroll
    for (int i = 0; i < 4; i++) {
        int r = rowBase + ty * 4 + i;
        float4 o;
        o.x = fmaxf(acc[i][0] + bj[0], 0.0f);
        o.y = fmaxf(acc[i][1] + bj[1], 0.0f);
        o.z = fmaxf(acc[i][2] + bj[2], 0.0f);
        o.w = fmaxf(acc[i][3] + bj[3], 0.0f);
        *reinterpret_cast<float4*>(&Cc[r * N + colBase + tx * 4]) = o;
    }
}

// ---------------------------------------------------------------------------
// Final FC: (B,128) @ (128,10) + bias, relu. One warp per batch row.
// ---------------------------------------------------------------------------
__global__ __launch_bounds__(256) void k_fc4(const float* __restrict__ w4,
                                             const float* __restrict__ b4,
                                             float* __restrict__ out) {
    int b = blockIdx.x * 8 + (threadIdx.x >> 5);
    int lane = threadIdx.x & 31;
    const float* row = &g_c3[b * 128];
    float v0 = row[lane], v1 = row[lane + 32], v2 = row[lane + 64], v3 = row[lane + 96];
    for (int j = 0; j < 10; j++) {
        float p = v0 * w4[lane * 10 + j]
                + v1 * w4[(lane + 32) * 10 + j]
                + v2 * w4[(lane + 64) * 10 + j]
                + v3 * w4[(lane + 96) * 10 + j];
        #pragma unroll
        for (int o = 16; o > 0; o >>= 1) p += __shfl_down_sync(0xffffffffu, p, o);
        if (lane == 0) out[b * 10 + j] = fmaxf(p + b4[j], 0.0f);
    }
}

// ---------------------------------------------------------------------------
// Launch
// ---------------------------------------------------------------------------
extern "C" void kernel_launch(void* const* d_in, const int* in_sizes, int n_in,
                              void* d_out, int out_size) {
    const float* x       = (const float*)d_in[0];
    const float* la_a    = (const float*)d_in[1];
    const float* la_b    = (const float*)d_in[2];
    const float* la_bias = (const float*)d_in[3];
    const float* bn1_g   = (const float*)d_in[4];
    const float* bn1_b   = (const float*)d_in[5];
    const float* a1_w    = (const float*)d_in[6];
    const float* a1_b    = (const float*)d_in[7];
    const float* e1_w    = (const float*)d_in[8];
    const float* e1_b    = (const float*)d_in[9];
    const float* bn2_g   = (const float*)d_in[10];
    const float* bn2_b   = (const float*)d_in[11];
    const float* e2_w    = (const float*)d_in[12];
    const float* e2_b    = (const float*)d_in[13];
    const float* f1_w    = (const float*)d_in[14];
    const float* f1_b    = (const float*)d_in[15];
    const float* fa_w    = (const float*)d_in[16];
    const float* fa_b    = (const float*)d_in[17];
    const float* bn3_g   = (const float*)d_in[18];
    const float* bn3_b   = (const float*)d_in[19];
    const float* f2_w    = (const float*)d_in[20];
    const float* f2_b    = (const float*)d_in[21];
    const float* w1      = (const float*)d_in[22];
    const float* b1      = (const float*)d_in[23];
    const float* w2      = (const float*)d_in[24];
    const float* b2      = (const float*)d_in[25];
    const float* w3      = (const float*)d_in[26];
    const float* b3      = (const float*)d_in[27];
    const float* w4      = (const float*)d_in[28];
    const float* b4      = (const float*)d_in[29];
    float* out = (float*)d_out;

    float *p_z = nullptr, *p_c1 = nullptr, *p_c2 = nullptr, *p_c3 = nullptr;
    cudaGetSymbolAddress((void**)&p_z,  g_z);
    cudaGetSymbolAddress((void**)&p_c1, g_c1);
    cudaGetSymbolAddress((void**)&p_c2, g_c2);
    cudaGetSymbolAddress((void**)&p_c3, g_c3);

    k_init<<<1, 512>>>(la_a, la_b);
    k_conv<<<NB, 256>>>(x, la_bias);
    k_bnfin1<<<1, 32>>>(bn1_g, bn1_b);
    k_branch<<<NB, 256>>>(a1_w, a1_b, e1_w, e1_b, f1_w, f1_b, fa_w, fa_b);
    k_bnfin23<<<1, 32>>>(bn2_g, bn2_b, bn3_g, bn3_b);
    k_zassm<<<NB, 256>>>(e2_w, e2_b, f2_w, f2_b);

    {
        dim3 g(1024 / 64, NB / 64);
        k_gemm_relu<<<g, 256>>>(p_z, w1, b1, p_c1, NB, 1024, 768);
    }
    {
        dim3 g(512 / 64, NB / 64);
        k_gemm_relu<<<g, 256>>>(p_c1, w2, b2, p_c2, NB, 512, 1024);
    }
    {
        dim3 g(128 / 64, NB / 64);
        k_gemm_relu<<<g, 256>>>(p_c2, w3, b3, p_c3, NB, 128, 512);
    }
    k_fc4<<<NB / 8, 256>>>(w4, b4, out);
}